// round 3
// baseline (speedup 1.0000x reference)
#include <cuda_runtime.h>
#include <math.h>

#define BB   256
#define DF1  64

// out layout: value [B,32,32,32] | weight [B,32,32] | wp [B,32,32]
#define WOFF      (8388608ull)
#define WPOFF     (8650752ull)

typedef unsigned long long ull;

__device__ float g_M [128 * 128];
__device__ float g_Mp[128 * 128];
__device__ float g_U [BB * 32 * DF1];
__device__ float g_V [BB * 32 * DF1];

// ---- packed f32x2 helpers ----
__device__ __forceinline__ ull pk2(float v) {
    ull r; asm("mov.b64 %0, {%1, %1};" : "=l"(r) : "f"(v)); return r;
}
__device__ __forceinline__ ull ffma2(ull a, ull b, ull c) {
    ull d; asm("fma.rn.f32x2 %0, %1, %2, %3;" : "=l"(d) : "l"(a), "l"(b), "l"(c)); return d;
}
__device__ __forceinline__ float2 upk2(ull v) {
    float2 f; asm("mov.b64 {%0, %1}, %2;" : "=f"(f.x), "=f"(f.y) : "l"(v)); return f;
}

__device__ __forceinline__ float warp_max(float v) {
    #pragma unroll
    for (int o = 16; o; o >>= 1) v = fmaxf(v, __shfl_xor_sync(0xffffffffu, v, o));
    return v;
}
__device__ __forceinline__ float warp_sum(float v) {
    #pragma unroll
    for (int o = 16; o; o >>= 1) v += __shfl_xor_sync(0xffffffffu, v, o);
    return v;
}

// ---------------------------------------------------------------------------
// Kernel 0: M = W_q @ W_k^T, Mp = W_qp @ W_kp^T. grid (32,4,2), split-K=2.
// ---------------------------------------------------------------------------
__global__ void k0_precompute(const float* __restrict__ Wq, const float* __restrict__ Wk,
                              const float* __restrict__ Wqp, const float* __restrict__ Wkp) {
    __shared__ float sA[4 * 128];
    __shared__ float sB[32 * 129];
    __shared__ float sR[4 * 32 * 2];
    const float* A  = blockIdx.z ? Wqp : Wq;
    const float* Bm = blockIdx.z ? Wkp : Wk;
    float* out      = blockIdx.z ? g_Mp : g_M;
    const int e0 = blockIdx.x * 4;
    const int c0 = blockIdx.y * 32;
    const int t  = threadIdx.x;
    for (int idx = t; idx < 512; idx += 256) sA[idx] = A[e0 * 128 + idx];
    for (int idx = t; idx < 4096; idx += 256) {
        int r = idx >> 7, d = idx & 127;
        sB[r * 129 + d] = Bm[(c0 + r) * 128 + d];
    }
    __syncthreads();
    const int kh = t >> 7, r = (t >> 5) & 3, c = t & 31;
    float acc = 0.f;
    const int d0 = kh * 64;
    #pragma unroll 8
    for (int d = 0; d < 64; ++d)
        acc = fmaf(sA[r * 128 + d0 + d], sB[c * 129 + d0 + d], acc);
    sR[(r * 32 + c) * 2 + kh] = acc;
    __syncthreads();
    if (t < 128) {
        int rr = t >> 5, cc = t & 31;
        out[(e0 + rr) * 128 + c0 + cc] = sR[(rr * 32 + cc) * 2] + sR[(rr * 32 + cc) * 2 + 1];
    }
}

// ---------------------------------------------------------------------------
// k1 GEMM building blocks. Warp w owns rows r0=4w..4w+3 of the 32-row tile.
// Xd = duplicated X in smem (ull per element, value in both halves), stride 129.
// ---------------------------------------------------------------------------
template <int K>
__device__ __forceinline__ void mmd(const ull* __restrict__ Xd,
                                    const float* __restrict__ W,   // [K][128] row-major
                                    ull acc[4][2], int r0, int l) {
    const ulonglong2* W4 = reinterpret_cast<const ulonglong2*>(W);
    #pragma unroll 4
    for (int e = 0; e < K; ++e) {
        ulonglong2 wv = W4[e * 32 + l];
        #pragma unroll
        for (int r = 0; r < 4; ++r) {
            ull xx = Xd[(r0 + r) * 129 + e];           // LDS.64 broadcast, pre-dup'd
            acc[r][0] = ffma2(xx, wv.x, acc[r][0]);
            acc[r][1] = ffma2(xx, wv.y, acc[r][1]);
        }
    }
}

// pk2 fallback path (X plain in smem, stride xstr)
template <int K>
__device__ __forceinline__ void mm_pk2(const float* __restrict__ X, int xstr,
                                       const float* __restrict__ W,
                                       ull acc[4][2], int r0, int l) {
    const ulonglong2* W4 = reinterpret_cast<const ulonglong2*>(W);
    #pragma unroll 4
    for (int e = 0; e < K; ++e) {
        ulonglong2 wv = W4[e * 32 + l];
        #pragma unroll
        for (int r = 0; r < 4; ++r) {
            ull xx = pk2(X[(r0 + r) * xstr + e]);
            acc[r][0] = ffma2(xx, wv.x, acc[r][0]);
            acc[r][1] = ffma2(xx, wv.y, acc[r][1]);
        }
    }
}

__device__ __forceinline__ void store_plain(float* __restrict__ Y, ull acc[4][2],
                                            int r0, int l) {
    #pragma unroll
    for (int r = 0; r < 4; ++r) {
        float2 p0 = upk2(acc[r][0]);
        float2 p1 = upk2(acc[r][1]);
        *reinterpret_cast<float4*>(&Y[(r0 + r) * 128 + 4 * l]) =
            make_float4(p0.x, p0.y, p1.x, p1.y);
    }
}

__device__ __forceinline__ void store_dup_tanh(float2* __restrict__ Yd, ull acc[4][2],
                                               int r0, int l) {
    #pragma unroll
    for (int r = 0; r < 4; ++r) {
        float2 p0 = upk2(acc[r][0]);
        float2 p1 = upk2(acc[r][1]);
        float v0 = tanhf(p0.x), v1 = tanhf(p0.y), v2 = tanhf(p1.x), v3 = tanhf(p1.y);
        float2* row = &Yd[(r0 + r) * 129 + 4 * l];
        row[0] = make_float2(v0, v0);
        row[1] = make_float2(v1, v1);
        row[2] = make_float2(v2, v2);
        row[3] = make_float2(v3, v3);
    }
}

// Y[32,64] = Xd(dup)[32,128] @ W[128,64]
__device__ __forceinline__ void mm64d(const ull* __restrict__ Xd,
                                      const float* __restrict__ W,
                                      float* __restrict__ Y, int r0, int l) {
    const ull* Wu = reinterpret_cast<const ull*>(W);
    ull acc[4] = {0, 0, 0, 0};
    #pragma unroll 4
    for (int e = 0; e < 128; ++e) {
        ull wv = Wu[e * 32 + l];
        #pragma unroll
        for (int r = 0; r < 4; ++r)
            acc[r] = ffma2(Xd[(r0 + r) * 129 + e], wv, acc[r]);
    }
    #pragma unroll
    for (int r = 0; r < 4; ++r)
        *reinterpret_cast<float2*>(&Y[(r0 + r) * 64 + 2 * l]) = upk2(acc[r]);
}

// V variant: V[row] = (Xd@W − A1[row]) / 32 streamed straight to gmem
__device__ __forceinline__ void mm64d_V(const ull* __restrict__ Xd,
                                        const float* __restrict__ W,
                                        const float* __restrict__ A1,
                                        float* __restrict__ gV, int r0, int l) {
    const ull* Wu = reinterpret_cast<const ull*>(W);
    ull acc[4] = {0, 0, 0, 0};
    #pragma unroll 4
    for (int e = 0; e < 128; ++e) {
        ull wv = Wu[e * 32 + l];
        #pragma unroll
        for (int r = 0; r < 4; ++r)
            acc[r] = ffma2(Xd[(r0 + r) * 129 + e], wv, acc[r]);
    }
    #pragma unroll
    for (int r = 0; r < 4; ++r) {
        float2 p = upk2(acc[r]);
        float2 a = *reinterpret_cast<const float2*>(&A1[(r0 + r) * 64 + 2 * l]);
        *reinterpret_cast<float2*>(&gV[(r0 + r) * 64 + 2 * l]) =
            make_float2((p.x - a.x) * 0.03125f, (p.y - a.y) * 0.03125f);
    }
}

// ---------------------------------------------------------------------------
// Kernel 1: one block per batch.
// ---------------------------------------------------------------------------
#define SM1_BYTES 112128
#define SOFTMAX_SCALE 0.08838834764831843f   // 1/sqrt(128)

extern "C" __global__ void __launch_bounds__(256, 2)
k1_batch(const float* __restrict__ states, const float* __restrict__ policies,
         const float* __restrict__ actions, const float* __restrict__ states_people,
         const float* __restrict__ actions_people,
         const float* __restrict__ Wv, const float* __restrict__ Wvp,
         const float* __restrict__ Wf1, float* __restrict__ out) {
    extern __shared__ __align__(16) unsigned char smraw[];
    float2* s_oad = reinterpret_cast<float2*>(smraw);            // 32 x 129 fl2 (dup)
    float2* s_vd  = s_oad + 4128;                                 // 32 x 129 fl2 (dup; early = t/tp plain)
    float*  s_oap = reinterpret_cast<float*>(s_vd + 4128);        // 32 x 133
    float*  s_D   = s_oap + 4256;                                 // 32 x 33
    float*  s_w   = s_D   + 1056;                                 // 32 x 33
    float*  s_wp  = s_w   + 1056;                                 // 32 x 33
    float*  s_A1  = s_wp  + 1056;                                 // 32 x 64  (early = sc)
    float*  s_C1  = s_A1  + 2048;                                 // 32 x 64  (early = sp)
    float*  s_sc  = s_A1;
    float*  s_sp  = s_C1;
    float*  t_pl  = reinterpret_cast<float*>(s_vd);               // t  [32][128]
    float*  tp_pl = t_pl + 4096;                                  // tp [32][128]
    const ull* oad_u = reinterpret_cast<const ull*>(s_oad);
    const ull* vd_u  = reinterpret_cast<const ull*>(s_vd);

    const int b = blockIdx.x;
    const int t = threadIdx.x;
    const int w = t >> 5, l = t & 31, r0 = 4 * w;

    // --- load inputs ---
    {
        const float* st  = states         + (size_t)b * 32 * 96;
        const float* ac  = actions        + (size_t)b * 1024;
        const float* stp = states_people  + (size_t)b * 32 * 96;
        const float* acp = actions_people + (size_t)b * 1024;
        const float* po  = policies       + (size_t)b * 1024;
        for (int idx = t; idx < 4096; idx += 256) {
            int i = idx >> 7, c = idx & 127;
            float voa = (c < 96) ? st [i * 96 + c] : ac [i * 32 + c - 96];
            s_oad[i * 129 + c] = make_float2(voa, voa);
            s_oap[i * 133 + c] = (c < 96) ? stp[i * 96 + c] : acp[i * 32 + c - 96];
        }
        for (int idx = t; idx < 1024; idx += 256)
            s_D[(idx >> 5) * 33 + (idx & 31)] = po[idx] - ac[idx];
    }
    __syncthreads();

    // --- t = oa @ M ; tp = oa @ Mp ---
    {
        ull a1[4][2] = {{0,0},{0,0},{0,0},{0,0}};
        mmd<128>(oad_u, g_M, a1, r0, l);
        store_plain(t_pl, a1, r0, l);
        ull a2[4][2] = {{0,0},{0,0},{0,0},{0,0}};
        mmd<128>(oad_u, g_Mp, a2, r0, l);
        store_plain(tp_pl, a2, r0, l);
    }

    // --- scores[i,j] = t[i]·oa[j] ; sp[n,p] = tp[n]·oap[p] ---
    {
        const float* oaf = reinterpret_cast<const float*>(s_oad);
        float a0 = 0, a1 = 0, a2 = 0, a3 = 0;
        float c0 = 0, c1 = 0, c2 = 0, c3 = 0;
        #pragma unroll 4
        for (int f = 0; f < 128; ++f) {
            float oj = oaf[2 * (l * 129 + f)];
            float pj = s_oap[l * 133 + f];
            a0 = fmaf(t_pl [(r0 + 0) * 128 + f], oj, a0);
            a1 = fmaf(t_pl [(r0 + 1) * 128 + f], oj, a1);
            a2 = fmaf(t_pl [(r0 + 2) * 128 + f], oj, a2);
            a3 = fmaf(t_pl [(r0 + 3) * 128 + f], oj, a3);
            c0 = fmaf(tp_pl[(r0 + 0) * 128 + f], pj, c0);
            c1 = fmaf(tp_pl[(r0 + 1) * 128 + f], pj, c1);
            c2 = fmaf(tp_pl[(r0 + 2) * 128 + f], pj, c2);
            c3 = fmaf(tp_pl[(r0 + 3) * 128 + f], pj, c3);
        }
        s_sc[(r0 + 0) * 33 + l] = a0;  s_sc[(r0 + 1) * 33 + l] = a1;
        s_sc[(r0 + 2) * 33 + l] = a2;  s_sc[(r0 + 3) * 33 + l] = a3;
        s_sp[(r0 + 0) * 33 + l] = c0;  s_sp[(r0 + 1) * 33 + l] = c1;
        s_sp[(r0 + 2) * 33 + l] = c2;  s_sp[(r0 + 3) * 33 + l] = c3;
    }
    __syncthreads();

    // --- column softmaxes ---
    {
        #pragma unroll
        for (int k = 0; k < 4; ++k) {
            int a = w + 8 * k;
            float v  = s_sc[l * 33 + a] * SOFTMAX_SCALE;
            float m  = warp_max(v);
            float e  = expf(v - m);
            float s  = warp_sum(e);
            float wg = e / s;
            s_w[a * 33 + l] = wg;
            out[WOFF + ((size_t)b * 32 + a) * 32 + l] = wg;
            float v2 = s_sp[l * 33 + a] * SOFTMAX_SCALE;
            float m2 = warp_max(v2);
            float e2 = expf(v2 - m2);
            float s2 = warp_sum(e2);
            s_wp[l * 33 + a] = e2 / s2;
        }
    }
    __syncthreads();   // protect sc/sp overlays and t/tp before vd/A1/C1 writes

    // --- va -> A1 ; vp -> V ; avp -> C1  (warp-private row chains) ---
    {
        ull av[4][2] = {{0,0},{0,0},{0,0},{0,0}};
        mmd<128>(oad_u, Wv, av, r0, l);
        store_dup_tanh(s_vd, av, r0, l);                    // va
        mm64d(vd_u, Wf1, s_A1, r0, l);                      // A1
        mm_pk2<32>(s_D, 33, Wv + 96 * 128, av, r0, l);      // += (pol-act) part
        store_dup_tanh(s_vd, av, r0, l);                    // vp
        mm64d_V(vd_u, Wf1, s_A1, g_V + (size_t)b * 2048, r0, l);   // V
        ull ap[4][2] = {{0,0},{0,0},{0,0},{0,0}};
        mm_pk2<128>(s_oap, 133, Wvp, ap, r0, l);
        store_dup_tanh(s_vd, ap, r0, l);                    // avp
        mm64d(vd_u, Wf1 + 128 * 64, s_C1, r0, l);           // C1
    }
    __syncthreads();

    // --- wp to global ---
    for (int idx = t; idx < 1024; idx += 256)
        out[WPOFF + (size_t)b * 1024 + idx] = s_wp[(idx >> 5) * 33 + (idx & 31)];

    // --- U[a,f] = (w[a,:]·A1[:,f] + wp[a,:]·C1[:,f]) / 32 ---
    for (int idx = t; idx < 2048; idx += 256) {
        int a = idx >> 6, f = idx & 63;
        float acc = 0.f;
        #pragma unroll
        for (int j = 0; j < 32; ++j) acc = fmaf(s_w [a * 33 + j], s_A1[j * 64 + f], acc);
        #pragma unroll
        for (int p = 0; p < 32; ++p) acc = fmaf(s_wp[a * 33 + p], s_C1[p * 64 + f], acc);
        g_U[(size_t)b * 2048 + idx] = acc * 0.03125f;
    }
}

// ---------------------------------------------------------------------------
// Kernel 2: value[b,a,i,:] = lrelu(U[b,a] + weight[b,a,i]*V[b,i]) @ W_f2
// grid 2048 = (b, a-quad). warp = (a, n-half), lane = i. W2 tiles in registers.
// ---------------------------------------------------------------------------
extern "C" __global__ void __launch_bounds__(256)
k2_value(const float* __restrict__ Wf2, float* __restrict__ out) {
    __shared__ float sV[32 * 65];
    __shared__ float sU[4 * 64];
    __shared__ float sw[4 * 33];
    const int t  = threadIdx.x;
    const int b  = blockIdx.x >> 3;
    const int a0 = (blockIdx.x & 7) * 4;

    for (int idx = t; idx < 2048; idx += 256) {
        int i = idx >> 6, f = idx & 63;
        sV[i * 65 + f] = g_V[(size_t)b * 2048 + idx];
    }
    if (t < 256) { /* all */ }
    for (int idx = t; idx < 256; idx += 256)
        sU[idx] = g_U[(size_t)b * 2048 + a0 * 64 + idx];
    if (t < 128) {
        int a = t >> 5, i = t & 31;
        sw[a * 33 + i] = out[WOFF + ((size_t)b * 32 + a0 + a) * 32 + i];
    }
    __syncthreads();

    const int w  = t >> 5, l = t & 31;
    const int aa = w >> 1;            // 0..3
    const int nh = w & 1;             // n-half
    const float wai = sw[aa * 33 + l];
    const float* Urow = &sU[aa * 64];

    ull acc[8];
    #pragma unroll
    for (int q = 0; q < 8; ++q) acc[q] = 0ull;

    #pragma unroll 4
    for (int tile = 0; tile < 16; ++tile) {
        ulonglong2 wreg[4][2];        // 4 f-rows x 16 cols (8 ull)
        ulonglong2 wreg2[4][2];
        #pragma unroll
        for (int ff = 0; ff < 4; ++ff) {
            const ulonglong2* p =
                reinterpret_cast<const ulonglong2*>(Wf2 + (tile * 4 + ff) * 32 + nh * 16);
            wreg[ff][0]  = p[0];  wreg[ff][1]  = p[1];
            wreg2[ff][0] = p[2];  wreg2[ff][1] = p[3];
        }
        #pragma unroll
        for (int ff = 0; ff < 4; ++ff) {
            int f = tile * 4 + ff;
            float h = fmaf(wai, sV[l * 65 + f], Urow[f]);
            h = fmaxf(h, 0.f) + 0.01f * fminf(h, 0.f);
            ull hh = pk2(h);
            acc[0] = ffma2(hh, wreg [ff][0].x, acc[0]);
            acc[1] = ffma2(hh, wreg [ff][0].y, acc[1]);
            acc[2] = ffma2(hh, wreg [ff][1].x, acc[2]);
            acc[3] = ffma2(hh, wreg [ff][1].y, acc[3]);
            acc[4] = ffma2(hh, wreg2[ff][0].x, acc[4]);
            acc[5] = ffma2(hh, wreg2[ff][0].y, acc[5]);
            acc[6] = ffma2(hh, wreg2[ff][1].x, acc[6]);
            acc[7] = ffma2(hh, wreg2[ff][1].y, acc[7]);
        }
    }

    float* op = out + (((size_t)b * 32 + a0 + aa) * 32 + l) * 32 + nh * 16;
    #pragma unroll
    for (int q = 0; q < 4; ++q) {
        float2 p0 = upk2(acc[2 * q]);
        float2 p1 = upk2(acc[2 * q + 1]);
        reinterpret_cast<float4*>(op)[q] = make_float4(p0.x, p0.y, p1.x, p1.y);
    }
}

// ---------------------------------------------------------------------------
extern "C" void kernel_launch(void* const* d_in, const int* in_sizes, int n_in,
                              void* d_out, int out_size) {
    const float* states         = (const float*)d_in[0];
    const float* policies       = (const float*)d_in[1];
    const float* actions        = (const float*)d_in[2];
    const float* states_people  = (const float*)d_in[3];
    const float* actions_people = (const float*)d_in[4];
    const float* Wk  = (const float*)d_in[5];
    const float* Wq  = (const float*)d_in[6];
    const float* Wv  = (const float*)d_in[7];
    const float* Wkp = (const float*)d_in[8];
    const float* Wqp = (const float*)d_in[9];
    const float* Wvp = (const float*)d_in[10];
    const float* Wf1 = (const float*)d_in[11];
    const float* Wf2 = (const float*)d_in[12];
    float* out = (float*)d_out;

    k0_precompute<<<dim3(32, 4, 2), 256>>>(Wq, Wk, Wqp, Wkp);

    cudaFuncSetAttribute(k1_batch, cudaFuncAttributeMaxDynamicSharedMemorySize, SM1_BYTES);
    k1_batch<<<256, 256, SM1_BYTES>>>(states, policies, actions,
                                      states_people, actions_people,
                                      Wv, Wvp, Wf1, out);

    k2_value<<<2048, 256>>>(Wf2, out);
}

// round 4
// speedup vs baseline: 1.3269x; 1.3269x over previous
#include <cuda_runtime.h>
#include <math.h>

#define BB   256

// out layout: value [B,32,32,32] | weight [B,32,32] | wp [B,32,32]
#define WOFF      (8388608ull)
#define WPOFF     (8650752ull)

typedef unsigned long long ull;

__device__ float g_M [128 * 128];
__device__ float g_Mp[128 * 128];
__device__ float g_U [BB * 32 * 64];
__device__ float g_V [BB * 32 * 64];

// ---- packed f32x2 helpers ----
__device__ __forceinline__ ull pk2(float v) {
    ull r; asm("mov.b64 %0, {%1, %1};" : "=l"(r) : "f"(v)); return r;
}
__device__ __forceinline__ ull ffma2(ull a, ull b, ull c) {
    ull d; asm("fma.rn.f32x2 %0, %1, %2, %3;" : "=l"(d) : "l"(a), "l"(b), "l"(c)); return d;
}
__device__ __forceinline__ float2 upk2(ull v) {
    float2 f; asm("mov.b64 {%0, %1}, %2;" : "=f"(f.x), "=f"(f.y) : "l"(v)); return f;
}

__device__ __forceinline__ float warp_max(float v) {
    #pragma unroll
    for (int o = 16; o; o >>= 1) v = fmaxf(v, __shfl_xor_sync(0xffffffffu, v, o));
    return v;
}
__device__ __forceinline__ float warp_sum(float v) {
    #pragma unroll
    for (int o = 16; o; o >>= 1) v += __shfl_xor_sync(0xffffffffu, v, o);
    return v;
}

// ---------------------------------------------------------------------------
// Kernel 0: M = W_q @ W_k^T, Mp = W_qp @ W_kp^T   (round-2 version)
// ---------------------------------------------------------------------------
__global__ void k0_precompute(const float* __restrict__ Wq, const float* __restrict__ Wk,
                              const float* __restrict__ Wqp, const float* __restrict__ Wkp) {
    __shared__ float sA[8 * 128];
    __shared__ float sB[64 * 129];
    const float* A  = blockIdx.z ? Wqp : Wq;
    const float* Bm = blockIdx.z ? Wkp : Wk;
    float* out      = blockIdx.z ? g_Mp : g_M;
    const int e0 = blockIdx.x * 8;
    const int c0 = blockIdx.y * 64;
    const int t  = threadIdx.x;
    for (int idx = t; idx < 1024; idx += 256) sA[idx] = A[e0 * 128 + idx];
    for (int idx = t; idx < 64 * 128; idx += 256) {
        int r = idx >> 7, d = idx & 127;
        sB[r * 129 + d] = Bm[(c0 + r) * 128 + d];
    }
    __syncthreads();
    const int w = t >> 5, l = t & 31;
    float a0 = 0.f, a1 = 0.f;
    #pragma unroll 8
    for (int d = 0; d < 128; ++d) {
        float av = sA[w * 128 + d];
        a0 = fmaf(av, sB[l * 129 + d], a0);
        a1 = fmaf(av, sB[(l + 32) * 129 + d], a1);
    }
    out[(e0 + w) * 128 + c0 + l]      = a0;
    out[(e0 + w) * 128 + c0 + 32 + l] = a1;
}

// ---------------------------------------------------------------------------
// GEMM helpers (round-2 pk2 style). Warp w owns rows r0=4w..4w+3.
// ---------------------------------------------------------------------------
template <int K>
__device__ __forceinline__ void mm_acc128(const float* __restrict__ X, int xstr,
                                          const float* __restrict__ W,
                                          ull acc[4][2], int r0, int l) {
    const ulonglong2* W4 = reinterpret_cast<const ulonglong2*>(W);
    #pragma unroll 4
    for (int e = 0; e < K; ++e) {
        ulonglong2 wv = W4[e * 32 + l];
        #pragma unroll
        for (int r = 0; r < 4; ++r) {
            ull xx = pk2(X[(r0 + r) * xstr + e]);
            acc[r][0] = ffma2(xx, wv.x, acc[r][0]);
            acc[r][1] = ffma2(xx, wv.y, acc[r][1]);
        }
    }
}

// delta part of vp: X rows live in registers d_r[4], broadcast via shfl
__device__ __forceinline__ void mm_acc128_shfl(const float d_r[4],
                                               const float* __restrict__ W,
                                               ull acc[4][2], int l) {
    const ulonglong2* W4 = reinterpret_cast<const ulonglong2*>(W);
    #pragma unroll 4
    for (int e = 0; e < 32; ++e) {
        ulonglong2 wv = W4[e * 32 + l];
        #pragma unroll
        for (int r = 0; r < 4; ++r) {
            ull xx = pk2(__shfl_sync(0xffffffffu, d_r[r], e));
            acc[r][0] = ffma2(xx, wv.x, acc[r][0]);
            acc[r][1] = ffma2(xx, wv.y, acc[r][1]);
        }
    }
}

__device__ __forceinline__ void store128(float* __restrict__ Y, ull acc[4][2],
                                         int r0, int l, bool do_tanh) {
    #pragma unroll
    for (int r = 0; r < 4; ++r) {
        float2 p0 = upk2(acc[r][0]);
        float2 p1 = upk2(acc[r][1]);
        float4 v = make_float4(p0.x, p0.y, p1.x, p1.y);
        if (do_tanh) { v.x = tanhf(v.x); v.y = tanhf(v.y); v.z = tanhf(v.z); v.w = tanhf(v.w); }
        *reinterpret_cast<float4*>(&Y[(r0 + r) * 128 + 4 * l]) = v;
    }
}

// Y[32,64] = X[32,128](stride 128) @ W[128,64]
__device__ __forceinline__ void mm64(const float* __restrict__ X,
                                     const float* __restrict__ W,
                                     float* __restrict__ Y, int r0, int l) {
    const ull* Wu = reinterpret_cast<const ull*>(W);
    ull acc[4] = {0, 0, 0, 0};
    #pragma unroll 4
    for (int e = 0; e < 128; ++e) {
        ull wv = Wu[e * 32 + l];
        #pragma unroll
        for (int r = 0; r < 4; ++r)
            acc[r] = ffma2(pk2(X[(r0 + r) * 128 + e]), wv, acc[r]);
    }
    #pragma unroll
    for (int r = 0; r < 4; ++r)
        *reinterpret_cast<float2*>(&Y[(r0 + r) * 64 + 2 * l]) = upk2(acc[r]);
}

// V variant: V[row] = (X@W − A1[row]) / 32 streamed straight to gmem
__device__ __forceinline__ void mm64_V(const float* __restrict__ X,
                                       const float* __restrict__ W,
                                       const float* __restrict__ A1,
                                       float* __restrict__ gV, int r0, int l) {
    const ull* Wu = reinterpret_cast<const ull*>(W);
    ull acc[4] = {0, 0, 0, 0};
    #pragma unroll 4
    for (int e = 0; e < 128; ++e) {
        ull wv = Wu[e * 32 + l];
        #pragma unroll
        for (int r = 0; r < 4; ++r)
            acc[r] = ffma2(pk2(X[(r0 + r) * 128 + e]), wv, acc[r]);
    }
    #pragma unroll
    for (int r = 0; r < 4; ++r) {
        float2 p = upk2(acc[r]);
        float2 a = *reinterpret_cast<const float2*>(&A1[(r0 + r) * 64 + 2 * l]);
        *reinterpret_cast<float2*>(&gV[(r0 + r) * 64 + 2 * l]) =
            make_float2((p.x - a.x) * 0.03125f, (p.y - a.y) * 0.03125f);
    }
}

// ---------------------------------------------------------------------------
// Kernel 1: one block per batch.  smem = 74,112 B -> 3 blocks/SM.
// ---------------------------------------------------------------------------
#define SM1_BYTES 74112
#define SOFTMAX_SCALE 0.08838834764831843f   // 1/sqrt(128)

extern "C" __global__ void __launch_bounds__(256, 3)
k1_batch(const float* __restrict__ states, const float* __restrict__ policies,
         const float* __restrict__ actions, const float* __restrict__ states_people,
         const float* __restrict__ actions_people,
         const float* __restrict__ Wv, const float* __restrict__ Wvp,
         const float* __restrict__ Wf1, float* __restrict__ out) {
    extern __shared__ __align__(16) float sm[];
    float* s_oa  = sm;                 // 32 x 129
    float* s_oap = s_oa  + 4128;       // 32 x 129
    float* s_t   = s_oap + 4128;       // 32 x 128  (t -> tp -> va -> vp -> avp, warp-local)
    float* s_w   = s_t   + 4096;       // 32 x 32
    float* s_wp  = s_w   + 1024;       // 32 x 33
    float* s_A1  = s_wp  + 1056;       // 32 x 64  (early: sc 32x33)
    float* s_C1  = s_A1  + 2048;       // 32 x 64  (early: sp 32x33)
    float* s_sc  = s_A1;
    float* s_sp  = s_C1;

    const int b = blockIdx.x;
    const int t = threadIdx.x;
    const int w = t >> 5, l = t & 31, r0 = 4 * w;

    const float* ac = actions  + (size_t)b * 1024;
    const float* po = policies + (size_t)b * 1024;

    // --- delta rows (pol - act) into registers, warp-local rows r0..r0+3 ---
    float d_r[4];
    #pragma unroll
    for (int r = 0; r < 4; ++r)
        d_r[r] = po[(r0 + r) * 32 + l] - ac[(r0 + r) * 32 + l];

    // --- load inputs ---
    {
        const float* st  = states         + (size_t)b * 32 * 96;
        const float* stp = states_people  + (size_t)b * 32 * 96;
        const float* acp = actions_people + (size_t)b * 1024;
        for (int idx = t; idx < 4096; idx += 256) {
            int i = idx >> 7, c = idx & 127;
            s_oa [i * 129 + c] = (c < 96) ? st [i * 96 + c] : ac [i * 32 + c - 96];
            s_oap[i * 129 + c] = (c < 96) ? stp[i * 96 + c] : acp[i * 32 + c - 96];
        }
    }
    __syncthreads();   // S1

    // --- t = oa @ M ; scores -> sc. then tp = oa @ Mp ; -> sp ---
    {
        ull a1[4][2] = {{0,0},{0,0},{0,0},{0,0}};
        mm_acc128<128>(s_oa, 129, g_M, a1, r0, l);
        store128(s_t, a1, r0, l, false);
        float a0 = 0, s1 = 0, s2 = 0, s3 = 0;
        #pragma unroll 4
        for (int f = 0; f < 128; ++f) {
            float oj = s_oa[l * 129 + f];
            a0 = fmaf(s_t[(r0 + 0) * 128 + f], oj, a0);
            s1 = fmaf(s_t[(r0 + 1) * 128 + f], oj, s1);
            s2 = fmaf(s_t[(r0 + 2) * 128 + f], oj, s2);
            s3 = fmaf(s_t[(r0 + 3) * 128 + f], oj, s3);
        }
        s_sc[(r0 + 0) * 33 + l] = a0;  s_sc[(r0 + 1) * 33 + l] = s1;
        s_sc[(r0 + 2) * 33 + l] = s2;  s_sc[(r0 + 3) * 33 + l] = s3;

        ull a2[4][2] = {{0,0},{0,0},{0,0},{0,0}};
        mm_acc128<128>(s_oa, 129, g_Mp, a2, r0, l);
        store128(s_t, a2, r0, l, false);
        float c0 = 0, c1 = 0, c2 = 0, c3 = 0;
        #pragma unroll 4
        for (int f = 0; f < 128; ++f) {
            float pj = s_oap[l * 129 + f];
            c0 = fmaf(s_t[(r0 + 0) * 128 + f], pj, c0);
            c1 = fmaf(s_t[(r0 + 1) * 128 + f], pj, c1);
            c2 = fmaf(s_t[(r0 + 2) * 128 + f], pj, c2);
            c3 = fmaf(s_t[(r0 + 3) * 128 + f], pj, c3);
        }
        s_sp[(r0 + 0) * 33 + l] = c0;  s_sp[(r0 + 1) * 33 + l] = c1;
        s_sp[(r0 + 2) * 33 + l] = c2;  s_sp[(r0 + 3) * 33 + l] = c3;
    }
    __syncthreads();   // S2

    // --- column softmaxes ---
    {
        #pragma unroll
        for (int k = 0; k < 4; ++k) {
            int a = w + 8 * k;
            float v  = s_sc[l * 33 + a] * SOFTMAX_SCALE;
            float m  = warp_max(v);
            float e  = expf(v - m);
            float s  = warp_sum(e);
            float wg = e / s;
            s_w[a * 32 + l] = wg;
            out[WOFF + ((size_t)b * 32 + a) * 32 + l] = wg;
            float v2 = s_sp[l * 33 + a] * SOFTMAX_SCALE;
            float m2 = warp_max(v2);
            float e2 = expf(v2 - m2);
            float s2 = warp_sum(e2);
            s_wp[l * 33 + a] = e2 / s2;
        }
    }
    __syncthreads();   // S3 (frees sc/sp regions for A1/C1)

    // --- va -> A1 ; vp -> V(gmem) ; avp -> C1  (warp-private chains) ---
    {
        ull av[4][2] = {{0,0},{0,0},{0,0},{0,0}};
        mm_acc128<128>(s_oa, 129, Wv, av, r0, l);
        store128(s_t, av, r0, l, true);                       // va
        mm64(s_t, Wf1, s_A1, r0, l);                          // A1
        mm_acc128_shfl(d_r, Wv + 96 * 128, av, l);            // += (pol-act)@Wv[96:]
        store128(s_t, av, r0, l, true);                       // vp
        mm64_V(s_t, Wf1, s_A1, g_V + (size_t)b * 2048, r0, l);  // V
        ull ap[4][2] = {{0,0},{0,0},{0,0},{0,0}};
        mm_acc128<128>(s_oap, 129, Wvp, ap, r0, l);
        store128(s_t, ap, r0, l, true);                       // avp
        mm64(s_t, Wf1 + 128 * 64, s_C1, r0, l);               // C1
    }
    __syncthreads();   // S4

    // --- wp to global ---
    for (int idx = t; idx < 1024; idx += 256)
        out[WPOFF + (size_t)b * 1024 + idx] = s_wp[(idx >> 5) * 33 + (idx & 31)];

    // --- U[a, 2l..2l+1] = (w[a,:]@A1 + wp[a,:]@C1)/32, warp rows r0..r0+3 ---
    {
        const ull* A1u = reinterpret_cast<const ull*>(s_A1);
        const ull* C1u = reinterpret_cast<const ull*>(s_C1);
        ull uacc[4] = {0, 0, 0, 0};
        #pragma unroll 4
        for (int j = 0; j < 32; ++j) {
            ull wv = A1u[j * 32 + l];
            #pragma unroll
            for (int r = 0; r < 4; ++r)
                uacc[r] = ffma2(pk2(s_w[(r0 + r) * 32 + j]), wv, uacc[r]);
        }
        #pragma unroll 4
        for (int p = 0; p < 32; ++p) {
            ull wv = C1u[p * 32 + l];
            #pragma unroll
            for (int r = 0; r < 4; ++r)
                uacc[r] = ffma2(pk2(s_wp[(r0 + r) * 33 + p]), wv, uacc[r]);
        }
        float* gU = g_U + (size_t)b * 2048;
        #pragma unroll
        for (int r = 0; r < 4; ++r) {
            float2 p = upk2(uacc[r]);
            *reinterpret_cast<float2*>(&gU[(r0 + r) * 64 + 2 * l]) =
                make_float2(p.x * 0.03125f, p.y * 0.03125f);
        }
    }
}

// ---------------------------------------------------------------------------
// Kernel 2 (round-2 version): value = lrelu(U + weight*V) @ W_f2
// grid 1024 (b, a-octet); warp = a, lane = i.
// ---------------------------------------------------------------------------
extern "C" __global__ void __launch_bounds__(256)
k2_value(const float* __restrict__ Wf2, float* __restrict__ out) {
    __shared__ float sU [8 * 64];
    __shared__ float sV [32 * 65];
    __shared__ __align__(16) float sW2[64 * 32];
    __shared__ float sW [8 * 33];
    const int t  = threadIdx.x;
    const int b  = blockIdx.x >> 2;
    const int a0 = (blockIdx.x & 3) * 8;

    for (int idx = t; idx < 2048; idx += 256) {
        int i = idx >> 6, f = idx & 63;
        sV[i * 65 + f] = g_V[(size_t)b * 2048 + idx];
    }
    for (int idx = t; idx < 512; idx += 256)
        sU[idx] = g_U[(size_t)b * 2048 + a0 * 64 + idx];
    for (int idx = t; idx < 2048; idx += 256) sW2[idx] = Wf2[idx];
    {
        int a = t >> 5, i = t & 31;
        sW[a * 33 + i] = out[WOFF + ((size_t)b * 32 + a0 + a) * 32 + i];
    }
    __syncthreads();

    const int w = t >> 5, l = t & 31;
    const float wai = sW[w * 33 + l];
    const float* Ua = &sU[w * 64];
    ull acc[16];
    #pragma unroll
    for (int q = 0; q < 16; ++q) acc[q] = 0ull;

    #pragma unroll 8
    for (int f = 0; f < 64; ++f) {
        float h = fmaf(wai, sV[l * 65 + f], Ua[f]);
        h = fmaxf(h, 0.f) + 0.01f * fminf(h, 0.f);       // leaky_relu(0.01)
        ull hh = pk2(h);
        const ulonglong2* row = reinterpret_cast<const ulonglong2*>(&sW2[f * 32]);
        #pragma unroll
        for (int q = 0; q < 8; ++q) {
            ulonglong2 wv = row[q];
            acc[2 * q]     = ffma2(hh, wv.x, acc[2 * q]);
            acc[2 * q + 1] = ffma2(hh, wv.y, acc[2 * q + 1]);
        }
    }
    float4* op = reinterpret_cast<float4*>(out + (((size_t)b * 32 + a0 + w) * 32 + l) * 32);
    #pragma unroll
    for (int q = 0; q < 8; ++q) {
        float2 p0 = upk2(acc[2 * q]);
        float2 p1 = upk2(acc[2 * q + 1]);
        op[q] = make_float4(p0.x, p0.y, p1.x, p1.y);
    }
}

// ---------------------------------------------------------------------------
extern "C" void kernel_launch(void* const* d_in, const int* in_sizes, int n_in,
                              void* d_out, int out_size) {
    const float* states         = (const float*)d_in[0];
    const float* policies       = (const float*)d_in[1];
    const float* actions        = (const float*)d_in[2];
    const float* states_people  = (const float*)d_in[3];
    const float* actions_people = (const float*)d_in[4];
    const float* Wk  = (const float*)d_in[5];
    const float* Wq  = (const float*)d_in[6];
    const float* Wv  = (const float*)d_in[7];
    const float* Wkp = (const float*)d_in[8];
    const float* Wqp = (const float*)d_in[9];
    const float* Wvp = (const float*)d_in[10];
    const float* Wf1 = (const float*)d_in[11];
    const float* Wf2 = (const float*)d_in[12];
    float* out = (float*)d_out;

    k0_precompute<<<dim3(16, 2, 2), 256>>>(Wq, Wk, Wqp, Wkp);

    cudaFuncSetAttribute(k1_batch, cudaFuncAttributeMaxDynamicSharedMemorySize, SM1_BYTES);
    k1_batch<<<256, 256, SM1_BYTES>>>(states, policies, actions,
                                      states_people, actions_people,
                                      Wv, Wvp, Wf1, out);

    k2_value<<<1024, 256>>>(Wf2, out);
}